// round 3
// baseline (speedup 1.0000x reference)
#include <cuda_runtime.h>

#define BSZ 32
#define NP  64
#define NN  (NP*NP)   // 4096

typedef unsigned long long u64;

// ---------------- device scratch ----------------
__device__ float g_QK[4 * BSZ * NN];      // Q, K1, K2, K3
__device__ float g_att[6 * BSZ * NN];     // attq1, attq2, attq3, Tjk, Tjl, Akl (pre-scaled 0.0625)
__device__ float g_anchor4[4 * BSZ * NP]; // per (k-quarter, b, i) partial sums

// ---------------- f32x2 packed helpers ----------------
__device__ __forceinline__ u64 pk2(float lo, float hi) {
    u64 r; asm("mov.b64 %0,{%1,%2};" : "=l"(r) : "f"(lo), "f"(hi)); return r;
}
__device__ __forceinline__ void upk2(float& lo, float& hi, u64 v) {
    asm("mov.b64 {%0,%1},%2;" : "=f"(lo), "=f"(hi) : "l"(v));
}
__device__ __forceinline__ u64 dup2(float x) { return pk2(x, x); }
__device__ __forceinline__ u64 add2(u64 a, u64 b) {
    u64 r; asm("add.rn.f32x2 %0,%1,%2;" : "=l"(r) : "l"(a), "l"(b)); return r;
}
__device__ __forceinline__ u64 mul2(u64 a, u64 b) {
    u64 r; asm("mul.rn.f32x2 %0,%1,%2;" : "=l"(r) : "l"(a), "l"(b)); return r;
}
__device__ __forceinline__ u64 fma2(u64 a, u64 b, u64 c) {
    u64 r; asm("fma.rn.f32x2 %0,%1,%2,%3;" : "=l"(r) : "l"(a), "l"(b), "l"(c)); return r;
}
__device__ __forceinline__ float tanh_(float x) {
    float y; asm("tanh.approx.f32 %0,%1;" : "=f"(y) : "f"(x)); return y;
}

// ---------------- k1: four 3->64 dense layers ----------------
__global__ void k1_dense(const float* __restrict__ pts,
                         const float* __restrict__ Wq,  const float* __restrict__ bq,
                         const float* __restrict__ Wk1, const float* __restrict__ bk1,
                         const float* __restrict__ Wk2, const float* __restrict__ bk2,
                         const float* __restrict__ Wk3, const float* __restrict__ bk3) {
    int blk = blockIdx.x;
    int b = blk >> 2, m = blk & 3;
    const float* W; const float* bias;
    if      (m == 0) { W = Wq;  bias = bq;  }
    else if (m == 1) { W = Wk1; bias = bk1; }
    else if (m == 2) { W = Wk2; bias = bk2; }
    else             { W = Wk3; bias = bk3; }
    for (int e = threadIdx.x; e < NN; e += blockDim.x) {
        int n = e >> 6, d = e & 63;
        const float* p = pts + (b * NP + n) * 3;
        float v = fmaf(p[0], W[d],
                  fmaf(p[1], W[64 + d],
                  fmaf(p[2], W[128 + d], bias[d])));
        g_QK[(m * BSZ + b) * NN + e] = v;
    }
}

// ---------------- k2: six N x N attention matrices ----------------
// out[r*64+c] = 0.0625 * dot(S1[c,:], S2[r,:])
// m0: attq1[i][j]  m1: attq2[i][k]  m2: attq3[i][l]
// m3: Tjk[k][j]    m4: Tjl[l][j]    m5: Akl[k][l]
__global__ void k2_att() {
    __shared__ float S1t[64 * 65];
    __shared__ float S2s[64 * 64];
    int blk = blockIdx.x;
    int b = blk / 6, m = blk % 6;
    const int s1tab[6] = {1, 2, 3, 1, 1, 3};
    const int s2tab[6] = {0, 0, 0, 2, 3, 2};
    const float* S1 = g_QK + (s1tab[m] * BSZ + b) * NN;
    const float* S2 = g_QK + (s2tab[m] * BSZ + b) * NN;
    for (int t = threadIdx.x; t < NN; t += blockDim.x) {
        int n = t >> 6, d = t & 63;
        S1t[d * 65 + n] = S1[t];
        S2s[t] = S2[t];
    }
    __syncthreads();
    const float cscale = 0.0625f;
    for (int e = threadIdx.x; e < NN; e += blockDim.x) {
        int r = e >> 6, c = e & 63;
        float acc = 0.f;
        #pragma unroll
        for (int d = 0; d < 64; d++)
            acc = fmaf(S1t[d * 65 + c], S2s[r * 64 + d], acc);
        g_att[(m * BSZ + b) * NN + e] = acc * cscale;
    }
}

// ---------------- pad: shifts ncu's single-capture slot onto k3 ----------------
__global__ void k_pad() {}

// ---------------- k3: 537M-eval gated-det core ----------------
// grid 8192 = B(32) x anchors(64) x k-quarters(4); block 128 (4 warps).
// warp owns k = k0 + warp + 4*t4 (4 k's); lane owns the (l, l+32) pair in f32x2.
// All broadcast operands pre-duplicated in smem -> zero dup-MOVs in inner loop.
__global__ void __launch_bounds__(128, 8) k3_core(const float* __restrict__ pts) {
    __shared__ ulonglong2 JA_s[64];      // ((x,x),(y,y)) per j   1KB
    __shared__ u64        JZ_s[64];      // (z,z)                 0.5KB
    __shared__ u64        Tk2_s[16*64];  // dup Tjk slice         8KB
    __shared__ u64        P2_s[64*32];   // [j][lane]={P(l,j),P(l+32,j)}  16KB
    __shared__ float4     D4_s[64];      // raw disp (for dk)     1KB
    __shared__ float      red_s[4];

    int bx = blockIdx.x;
    int q  = bx & 3;
    int i  = (bx >> 2) & 63;
    int b  = bx >> 8;
    int k0 = q * 16;
    int tid = threadIdx.x, warp = tid >> 5, lane = tid & 31;

    const float* attq1 = g_att + (0 * BSZ + b) * NN;
    const float* attq2 = g_att + (1 * BSZ + b) * NN;
    const float* attq3 = g_att + (2 * BSZ + b) * NN;
    const float* Tjk   = g_att + (3 * BSZ + b) * NN;
    const float* Tjl   = g_att + (4 * BSZ + b) * NN;
    const float* Akl   = g_att + (5 * BSZ + b) * NN;

    // ---- prep ----
    {
        const float* pi = pts + (b * NP + i) * 3;
        float pix = pi[0], piy = pi[1], piz = pi[2];
        if (tid < 64) {
            const float* pp = pts + (b * NP + tid) * 3;
            float dx = pp[0] - pix, dy = pp[1] - piy, dz = pp[2] - piz;
            D4_s[tid] = make_float4(dx, dy, dz, 0.f);
            ulonglong2 v; v.x = pk2(dx, dx); v.y = pk2(dy, dy);
            JA_s[tid] = v;
            JZ_s[tid] = pk2(dz, dz);
        }
    }
    for (int t = tid; t < 16 * 64; t += 128) {          // dup Tjk slice
        float v = Tjk[k0 * 64 + t];
        Tk2_s[t] = pk2(v, v);
    }
    for (int t = tid; t < 2048; t += 128) {             // fused P pairs
        int lp = t & 31, j = t >> 5;
        float a1j = attq1[i * 64 + j];
        float lo = Tjl[lp * 64 + j]        + a1j + attq3[i * 64 + lp];
        float hi = Tjl[(lp + 32) * 64 + j] + a1j + attq3[i * 64 + lp + 32];
        P2_s[j * 32 + lp] = pk2(lo, hi);
    }
    __syncthreads();

    // per-lane packed dl for (l=lane, l+32) — loop-invariant
    float4 da = D4_s[lane], db = D4_s[lane + 32];
    u64 dlx2 = pk2(da.x, db.x);
    u64 dly2 = pk2(da.y, db.y);
    u64 dlz2 = pk2(da.z, db.z);
    u64 half2c = dup2(0.5f);
    u64 acc2 = pk2(0.f, 0.f);

    #pragma unroll 1
    for (int t4 = 0; t4 < 4; t4++) {
        int kk = warp + 4 * t4;                 // uniform within warp
        int k  = k0 + kk;
        float4 dk = D4_s[k];
        float aik = __ldg(attq2 + i * 64 + k);
        const float* AklRow = Akl + k * 64;
        u64 base2 = pk2(aik + __ldg(AklRow + lane), aik + __ldg(AklRow + lane + 32));
        u64 cx2 = fma2(dup2(dk.y), dlz2, mul2(dup2(-dk.z), dly2));
        u64 cy2 = fma2(dup2(dk.z), dlx2, mul2(dup2(-dk.x), dlz2));
        u64 cz2 = fma2(dup2(dk.x), dly2, mul2(dup2(-dk.y), dlx2));
        const u64* Tk = Tk2_s + kk * 64;

        #pragma unroll 8
        for (int j = 0; j < 64; j++) {
            ulonglong2 jv = JA_s[j];              // LDS.128 broadcast: djx2, djy2
            u64 djz2 = JZ_s[j];                   // LDS.64 broadcast
            u64 tk2  = Tk[j];                     // LDS.64 broadcast (pre-dup)
            u64 p2   = P2_s[j * 32 + lane];       // LDS.64 conflict-free
            u64 e2   = add2(p2, add2(tk2, base2));
            float elo, ehi; upk2(elo, ehi, e2);
            float tlo = tanh_(elo);               // sigmoid = 0.5 + 0.5*tanh
            float thi = tanh_(ehi);
            u64 det2 = fma2(jv.x, cx2, fma2(jv.y, cy2, mul2(djz2, cz2)));
            u64 d2 = mul2(det2, det2);
            u64 g2 = fma2(pk2(tlo, thi), half2c, half2c);
            acc2 = fma2(d2, g2, acc2);
        }
    }

    // ---- reduction ----
    float alo, ahi; upk2(alo, ahi, acc2);
    float acc = alo + ahi;
    #pragma unroll
    for (int o = 16; o; o >>= 1) acc += __shfl_down_sync(0xffffffffu, acc, o);
    if (lane == 0) red_s[warp] = acc;
    __syncthreads();
    if (tid == 0) {
        float s = red_s[0] + red_s[1] + red_s[2] + red_s[3];
        g_anchor4[q * BSZ * NP + b * NP + i] = s;
    }
}

// ---------------- k4: pooled -> gelu MLP head (warp per batch) ----------------
__global__ void k4_head(const float* __restrict__ W1, const float* __restrict__ b1,
                        const float* __restrict__ W2, const float* __restrict__ b2,
                        float* __restrict__ out) {
    int warp = threadIdx.x >> 5, lane = threadIdx.x & 31;
    int b = warp;
    float s = 0.f;
    #pragma unroll
    for (int qq = 0; qq < 4; qq++)
        s += g_anchor4[qq * BSZ * NP + b * 64 + lane]
           + g_anchor4[qq * BSZ * NP + b * 64 + lane + 32];
    #pragma unroll
    for (int o = 16; o; o >>= 1) s += __shfl_xor_sync(0xffffffffu, s, o);
    float pooled = s * (1.f / 16777216.f);         // / (N^3 * N)
    float x  = fmaf(pooled, W1[lane], b1[lane]);   // lane = hidden unit
    float x3 = x * x * x;
    float t  = tanhf(0.7978845608028654f * fmaf(0.044715f, x3, x));
    float hc = 0.5f * x * (1.f + t);               // tanh-approx gelu
    float y  = hc * W2[lane];
    #pragma unroll
    for (int o = 16; o; o >>= 1) y += __shfl_xor_sync(0xffffffffu, y, o);
    if (lane == 0) out[b] = y + b2[0];
}

// ---------------- launch ----------------
extern "C" void kernel_launch(void* const* d_in, const int* in_sizes, int n_in,
                              void* d_out, int out_size) {
    const float* pts = (const float*)d_in[0];
    const float* Wq  = (const float*)d_in[1];
    const float* bq  = (const float*)d_in[2];
    const float* Wk1 = (const float*)d_in[3];
    const float* bk1 = (const float*)d_in[4];
    const float* Wk2 = (const float*)d_in[5];
    const float* bk2 = (const float*)d_in[6];
    const float* Wk3 = (const float*)d_in[7];
    const float* bk3 = (const float*)d_in[8];
    const float* W1  = (const float*)d_in[9];
    const float* b1  = (const float*)d_in[10];
    const float* W2  = (const float*)d_in[11];
    const float* b2  = (const float*)d_in[12];
    float* out = (float*)d_out;

    k1_dense<<<BSZ * 4, 256>>>(pts, Wq, bq, Wk1, bk1, Wk2, bk2, Wk3, bk3);
    k2_att<<<BSZ * 6, 256>>>();
    k_pad<<<1, 32>>>();                       // shifts ncu capture slot onto k3
    k3_core<<<BSZ * NP * 4, 128>>>(pts);
    k4_head<<<1, BSZ * 32>>>(W1, b1, W2, b2, out);
}

// round 4
// speedup vs baseline: 1.3896x; 1.3896x over previous
#include <cuda_runtime.h>

#define BSZ 32
#define NP  64
#define NN  (NP*NP)   // 4096

typedef unsigned long long u64;

// ---------------- device scratch ----------------
__device__ float g_QK[4 * BSZ * NN];      // Q, K1, K2, K3
__device__ float g_att[6 * BSZ * NN];     // attq1, attq2, attq3, Tjk, Tjl, Akl (pre-scaled 0.0625)
__device__ float g_anchor2[2 * BSZ * NP]; // per (k-half, b, i) partial sums

// ---------------- f32x2 packed helpers ----------------
__device__ __forceinline__ u64 pk2(float lo, float hi) {
    u64 r; asm("mov.b64 %0,{%1,%2};" : "=l"(r) : "f"(lo), "f"(hi)); return r;
}
__device__ __forceinline__ void upk2(float& lo, float& hi, u64 v) {
    asm("mov.b64 {%0,%1},%2;" : "=f"(lo), "=f"(hi) : "l"(v));
}
__device__ __forceinline__ u64 dup2(float x) { return pk2(x, x); }
__device__ __forceinline__ u64 add2(u64 a, u64 b) {
    u64 r; asm("add.rn.f32x2 %0,%1,%2;" : "=l"(r) : "l"(a), "l"(b)); return r;
}
__device__ __forceinline__ u64 mul2(u64 a, u64 b) {
    u64 r; asm("mul.rn.f32x2 %0,%1,%2;" : "=l"(r) : "l"(a), "l"(b)); return r;
}
__device__ __forceinline__ u64 fma2(u64 a, u64 b, u64 c) {
    u64 r; asm("fma.rn.f32x2 %0,%1,%2,%3;" : "=l"(r) : "l"(a), "l"(b), "l"(c)); return r;
}
__device__ __forceinline__ float tanh_(float x) {
    float y; asm("tanh.approx.f32 %0,%1;" : "=f"(y) : "f"(x)); return y;
}

// ---------------- k1: four 3->64 dense layers ----------------
__global__ void k1_dense(const float* __restrict__ pts,
                         const float* __restrict__ Wq,  const float* __restrict__ bq,
                         const float* __restrict__ Wk1, const float* __restrict__ bk1,
                         const float* __restrict__ Wk2, const float* __restrict__ bk2,
                         const float* __restrict__ Wk3, const float* __restrict__ bk3) {
    int blk = blockIdx.x;
    int b = blk >> 2, m = blk & 3;
    const float* W; const float* bias;
    if      (m == 0) { W = Wq;  bias = bq;  }
    else if (m == 1) { W = Wk1; bias = bk1; }
    else if (m == 2) { W = Wk2; bias = bk2; }
    else             { W = Wk3; bias = bk3; }
    for (int e = threadIdx.x; e < NN; e += blockDim.x) {
        int n = e >> 6, d = e & 63;
        const float* p = pts + (b * NP + n) * 3;
        float v = fmaf(p[0], W[d],
                  fmaf(p[1], W[64 + d],
                  fmaf(p[2], W[128 + d], bias[d])));
        g_QK[(m * BSZ + b) * NN + e] = v;
    }
}

// ---------------- k2: six N x N attention matrices ----------------
// out[r*64+c] = 0.0625 * dot(S1[c,:], S2[r,:])
// m0: attq1[i][j]  m1: attq2[i][k]  m2: attq3[i][l]
// m3: Tjk[k][j]    m4: Tjl[l][j]    m5: Akl[k][l]
__global__ void k2_att() {
    __shared__ float S1t[64 * 65];
    __shared__ float S2s[64 * 64];
    int blk = blockIdx.x;
    int b = blk / 6, m = blk % 6;
    const int s1tab[6] = {1, 2, 3, 1, 1, 3};
    const int s2tab[6] = {0, 0, 0, 2, 3, 2};
    const float* S1 = g_QK + (s1tab[m] * BSZ + b) * NN;
    const float* S2 = g_QK + (s2tab[m] * BSZ + b) * NN;
    for (int t = threadIdx.x; t < NN; t += blockDim.x) {
        int n = t >> 6, d = t & 63;
        S1t[d * 65 + n] = S1[t];
        S2s[t] = S2[t];
    }
    __syncthreads();
    const float cscale = 0.0625f;
    for (int e = threadIdx.x; e < NN; e += blockDim.x) {
        int r = e >> 6, c = e & 63;
        float acc = 0.f;
        #pragma unroll
        for (int d = 0; d < 64; d++)
            acc = fmaf(S1t[d * 65 + c], S2s[r * 64 + d], acc);
        g_att[(m * BSZ + b) * NN + e] = acc * cscale;
    }
}

// ---------------- pad: shifts ncu's single-capture slot onto k3 ----------------
__global__ void k_pad() {}

// ---------------- k3: 537M-eval gated-det core ----------------
// grid 4096 = B(32) x anchors(64) x k-halves(2); block 128 (4 warps).
// Warp owns 8 k's; per t-iter each lane handles k_a=k0+8w+t and k_b=k_a+4,
// with the (l=lane, l+32) pair packed in f32x2 -> 4 evals/lane/j.
// Broadcast stream per j: 3 scalar LDS (dj SoA) + 1 LDS.64 (tk pair).
__global__ void __launch_bounds__(128, 8) k3_core(const float* __restrict__ pts) {
    __shared__ float  DJX_s[64], DJY_s[64], DJZ_s[64];  // 768B, scalar broadcasts
    __shared__ u64    T2_s[4 * 4 * 64];  // [warp][t][j] = (Tjk[ka][j], Tjk[kb][j])  8KB
    __shared__ u64    P2_s[64 * 32];     // [j][lane] = {P(l,j), P(l+32,j)}  16KB
    __shared__ float4 D4_s[64];          // raw disp  1KB
    __shared__ float  red_s[4];

    int bx = blockIdx.x;
    int h  = bx & 1;
    int i  = (bx >> 1) & 63;
    int b  = bx >> 7;
    int k0 = h * 32;
    int tid = threadIdx.x, warp = tid >> 5, lane = tid & 31;

    const float* attq1 = g_att + (0 * BSZ + b) * NN;
    const float* attq2 = g_att + (1 * BSZ + b) * NN;
    const float* attq3 = g_att + (2 * BSZ + b) * NN;
    const float* Tjk   = g_att + (3 * BSZ + b) * NN;
    const float* Tjl   = g_att + (4 * BSZ + b) * NN;
    const float* Akl   = g_att + (5 * BSZ + b) * NN;

    // ---- prep ----
    {
        const float* pi = pts + (b * NP + i) * 3;
        float pix = pi[0], piy = pi[1], piz = pi[2];
        if (tid < 64) {
            const float* pp = pts + (b * NP + tid) * 3;
            float dx = pp[0] - pix, dy = pp[1] - piy, dz = pp[2] - piz;
            D4_s[tid]  = make_float4(dx, dy, dz, 0.f);
            DJX_s[tid] = dx; DJY_s[tid] = dy; DJZ_s[tid] = dz;
        }
    }
    for (int idx = tid; idx < 1024; idx += 128) {       // Tjk pairs for this k-half
        int w = idx >> 8, r = idx & 255;
        int t = r >> 6,   j = r & 63;
        int ka = k0 + 8 * w + t;
        T2_s[idx] = pk2(Tjk[ka * 64 + j], Tjk[(ka + 4) * 64 + j]);
    }
    for (int t = tid; t < 2048; t += 128) {             // fused P pairs
        int lp = t & 31, j = t >> 5;
        float a1j = attq1[i * 64 + j];
        float lo = Tjl[lp * 64 + j]        + a1j + attq3[i * 64 + lp];
        float hi = Tjl[(lp + 32) * 64 + j] + a1j + attq3[i * 64 + lp + 32];
        P2_s[j * 32 + lp] = pk2(lo, hi);
    }
    __syncthreads();

    // per-lane packed dl for (l=lane, l+32) — loop-invariant
    float4 da = D4_s[lane], db = D4_s[lane + 32];
    u64 dlx2 = pk2(da.x, db.x);
    u64 dly2 = pk2(da.y, db.y);
    u64 dlz2 = pk2(da.z, db.z);
    u64 half2c = dup2(0.5f);
    u64 acc2 = pk2(0.f, 0.f);

    #pragma unroll 1
    for (int t4 = 0; t4 < 4; t4++) {
        int ka = k0 + 8 * warp + t4;             // uniform within warp
        int kb = ka + 4;
        float4 dka = D4_s[ka];
        float4 dkb = D4_s[kb];
        float aika = __ldg(attq2 + i * 64 + ka);
        float aikb = __ldg(attq2 + i * 64 + kb);
        u64 base2a = pk2(aika + __ldg(Akl + ka * 64 + lane),
                         aika + __ldg(Akl + ka * 64 + lane + 32));
        u64 base2b = pk2(aikb + __ldg(Akl + kb * 64 + lane),
                         aikb + __ldg(Akl + kb * 64 + lane + 32));
        u64 cxa2 = fma2(dup2(dka.y), dlz2, mul2(dup2(-dka.z), dly2));
        u64 cya2 = fma2(dup2(dka.z), dlx2, mul2(dup2(-dka.x), dlz2));
        u64 cza2 = fma2(dup2(dka.x), dly2, mul2(dup2(-dka.y), dlx2));
        u64 cxb2 = fma2(dup2(dkb.y), dlz2, mul2(dup2(-dkb.z), dly2));
        u64 cyb2 = fma2(dup2(dkb.z), dlx2, mul2(dup2(-dkb.x), dlz2));
        u64 czb2 = fma2(dup2(dkb.x), dly2, mul2(dup2(-dkb.y), dlx2));
        const u64* Trow = T2_s + (warp * 4 + t4) * 64;

        #pragma unroll 8
        for (int j = 0; j < 64; j++) {
            float jx = DJX_s[j];                   // LDS.32 bcast (1 wf)
            float jy = DJY_s[j];                   // LDS.32 bcast
            float jz = DJZ_s[j];                   // LDS.32 bcast
            u64 tt = Trow[j];                      // LDS.64 bcast (2 wf)
            u64 p2 = P2_s[j * 32 + lane];          // LDS.64 per-lane (2 wf)
            float tka, tkb; upk2(tka, tkb, tt);
            u64 ea2 = add2(p2, add2(dup2(tka), base2a));
            u64 eb2 = add2(p2, add2(dup2(tkb), base2b));
            float ealo, eahi; upk2(ealo, eahi, ea2);
            float eblo, ebhi; upk2(eblo, ebhi, eb2);
            float ta_lo = tanh_(ealo), ta_hi = tanh_(eahi);
            float tb_lo = tanh_(eblo), tb_hi = tanh_(ebhi);
            u64 jx2 = dup2(jx), jy2 = dup2(jy), jz2 = dup2(jz);
            u64 deta = fma2(jx2, cxa2, fma2(jy2, cya2, mul2(jz2, cza2)));
            u64 detb = fma2(jx2, cxb2, fma2(jy2, cyb2, mul2(jz2, czb2)));
            u64 d2a = mul2(deta, deta);
            u64 d2b = mul2(detb, detb);
            u64 g2a = fma2(pk2(ta_lo, ta_hi), half2c, half2c);
            u64 g2b = fma2(pk2(tb_lo, tb_hi), half2c, half2c);
            acc2 = fma2(d2a, g2a, acc2);
            acc2 = fma2(d2b, g2b, acc2);
        }
    }

    // ---- reduction ----
    float alo, ahi; upk2(alo, ahi, acc2);
    float acc = alo + ahi;
    #pragma unroll
    for (int o = 16; o; o >>= 1) acc += __shfl_down_sync(0xffffffffu, acc, o);
    if (lane == 0) red_s[warp] = acc;
    __syncthreads();
    if (tid == 0) {
        float s = red_s[0] + red_s[1] + red_s[2] + red_s[3];
        g_anchor2[h * BSZ * NP + b * NP + i] = s;
    }
}

// ---------------- k4: pooled -> gelu MLP head (warp per batch) ----------------
__global__ void k4_head(const float* __restrict__ W1, const float* __restrict__ b1,
                        const float* __restrict__ W2, const float* __restrict__ b2,
                        float* __restrict__ out) {
    int warp = threadIdx.x >> 5, lane = threadIdx.x & 31;
    int b = warp;
    float s = g_anchor2[b * 64 + lane] + g_anchor2[b * 64 + lane + 32]
            + g_anchor2[BSZ * NP + b * 64 + lane] + g_anchor2[BSZ * NP + b * 64 + lane + 32];
    #pragma unroll
    for (int o = 16; o; o >>= 1) s += __shfl_xor_sync(0xffffffffu, s, o);
    float pooled = s * (1.f / 16777216.f);         // / (N^3 * N)
    float x  = fmaf(pooled, W1[lane], b1[lane]);   // lane = hidden unit
    float x3 = x * x * x;
    float t  = tanhf(0.7978845608028654f * fmaf(0.044715f, x3, x));
    float hc = 0.5f * x * (1.f + t);               // tanh-approx gelu
    float y  = hc * W2[lane];
    #pragma unroll
    for (int o = 16; o; o >>= 1) y += __shfl_xor_sync(0xffffffffu, y, o);
    if (lane == 0) out[b] = y + b2[0];
}

// ---------------- launch ----------------
extern "C" void kernel_launch(void* const* d_in, const int* in_sizes, int n_in,
                              void* d_out, int out_size) {
    const float* pts = (const float*)d_in[0];
    const float* Wq  = (const float*)d_in[1];
    const float* bq  = (const float*)d_in[2];
    const float* Wk1 = (const float*)d_in[3];
    const float* bk1 = (const float*)d_in[4];
    const float* Wk2 = (const float*)d_in[5];
    const float* bk2 = (const float*)d_in[6];
    const float* Wk3 = (const float*)d_in[7];
    const float* bk3 = (const float*)d_in[8];
    const float* W1  = (const float*)d_in[9];
    const float* b1  = (const float*)d_in[10];
    const float* W2  = (const float*)d_in[11];
    const float* b2  = (const float*)d_in[12];
    float* out = (float*)d_out;

    k1_dense<<<BSZ * 4, 256>>>(pts, Wq, bq, Wk1, bk1, Wk2, bk2, Wk3, bk3);
    k2_att<<<BSZ * 6, 256>>>();
    k_pad<<<1, 32>>>();                       // shifts ncu capture slot onto k3
    k3_core<<<BSZ * NP * 2, 128>>>(pts);
    k4_head<<<1, BSZ * 32>>>(W1, b1, W2, b2, out);
}

// round 5
// speedup vs baseline: 1.4067x; 1.0123x over previous
#include <cuda_runtime.h>

#define BSZ 32
#define NP  64
#define NN  (NP*NP)   // 4096

typedef unsigned long long u64;

// ---------------- device scratch ----------------
__device__ float g_att[6 * BSZ * NN];     // attq1, attq2, attq3, Tjk, Tjl, Akl (pre-scaled 0.0625)
__device__ float g_anchor2[2 * BSZ * NP]; // per (k-half, b, i) partial sums

// ---------------- f32x2 packed helpers ----------------
__device__ __forceinline__ u64 pk2(float lo, float hi) {
    u64 r; asm("mov.b64 %0,{%1,%2};" : "=l"(r) : "f"(lo), "f"(hi)); return r;
}
__device__ __forceinline__ void upk2(float& lo, float& hi, u64 v) {
    asm("mov.b64 {%0,%1},%2;" : "=f"(lo), "=f"(hi) : "l"(v));
}
__device__ __forceinline__ u64 dup2(float x) { return pk2(x, x); }
__device__ __forceinline__ u64 add2(u64 a, u64 b) {
    u64 r; asm("add.rn.f32x2 %0,%1,%2;" : "=l"(r) : "l"(a), "l"(b)); return r;
}
__device__ __forceinline__ u64 mul2(u64 a, u64 b) {
    u64 r; asm("mul.rn.f32x2 %0,%1,%2;" : "=l"(r) : "l"(a), "l"(b)); return r;
}
__device__ __forceinline__ u64 fma2(u64 a, u64 b, u64 c) {
    u64 r; asm("fma.rn.f32x2 %0,%1,%2,%3;" : "=l"(r) : "l"(a), "l"(b), "l"(c)); return r;
}
__device__ __forceinline__ float tanh_(float x) {
    float y; asm("tanh.approx.f32 %0,%1;" : "=f"(y) : "f"(x)); return y;
}

// ---------------- k12: fused dense + six N x N attention matrices ----------------
// grid 192 = B*6. Each block computes its two 64x64 feature matrices directly
// from pts (3 FMAs/elem), then the 64-deep dot products.
// out[r*64+c] = 0.0625 * dot(S1[c,:], S2[r,:])
// m0: attq1[i][j] (S1=K1,S2=Q)   m3: Tjk[k][j] (S1=K1,S2=K2)
// m1: attq2[i][k] (S1=K2,S2=Q)   m4: Tjl[l][j] (S1=K1,S2=K3)
// m2: attq3[i][l] (S1=K3,S2=Q)   m5: Akl[k][l] (S1=K3,S2=K2)
__global__ void k12_att(const float* __restrict__ pts,
                        const float* __restrict__ Wq,  const float* __restrict__ bq,
                        const float* __restrict__ Wk1, const float* __restrict__ bk1,
                        const float* __restrict__ Wk2, const float* __restrict__ bk2,
                        const float* __restrict__ Wk3, const float* __restrict__ bk3) {
    __shared__ float S1t[64 * 65];
    __shared__ float S2s[64 * 64];
    int blk = blockIdx.x;
    int b = blk / 6, m = blk % 6;
    const int s1tab[6] = {1, 2, 3, 1, 1, 3};
    const int s2tab[6] = {0, 0, 0, 2, 3, 2};
    int s1 = s1tab[m], s2 = s2tab[m];
    const float* WA; const float* bA;
    const float* WB; const float* bB;
    if      (s1 == 1) { WA = Wk1; bA = bk1; }
    else if (s1 == 2) { WA = Wk2; bA = bk2; }
    else              { WA = Wk3; bA = bk3; }
    if      (s2 == 0) { WB = Wq;  bB = bq;  }
    else if (s2 == 2) { WB = Wk2; bB = bk2; }
    else              { WB = Wk3; bB = bk3; }
    for (int t = threadIdx.x; t < NN; t += blockDim.x) {
        int n = t >> 6, d = t & 63;
        const float* p = pts + (b * NP + n) * 3;
        float v1 = fmaf(p[0], WA[d], fmaf(p[1], WA[64 + d], fmaf(p[2], WA[128 + d], bA[d])));
        float v2 = fmaf(p[0], WB[d], fmaf(p[1], WB[64 + d], fmaf(p[2], WB[128 + d], bB[d])));
        S1t[d * 65 + n] = v1;
        S2s[n * 64 + d] = v2;
    }
    __syncthreads();
    const float cscale = 0.0625f;
    for (int e = threadIdx.x; e < NN; e += blockDim.x) {
        int r = e >> 6, c = e & 63;
        float acc = 0.f;
        #pragma unroll
        for (int d = 0; d < 64; d++)
            acc = fmaf(S1t[d * 65 + c], S2s[r * 64 + d], acc);
        g_att[(m * BSZ + b) * NN + e] = acc * cscale;
    }
}

// ---------------- pad: keeps ncu's capture slot on k3 ----------------
__global__ void k_pad() {}

// ---------------- k3: 537M-eval gated-det core ----------------
// grid 4096 = B(32) x anchors(64) x k-halves(2); block 128 (4 warps).
// Warp owns 8 k's; per t4-iter each lane handles k_a and k_b=k_a+4,
// with the (l=lane, l+32) pair packed in f32x2 -> 4 evals/lane/j.
// All det-path broadcast operands pre-dup'd in smem; split accumulators.
__global__ void __launch_bounds__(128, 8) k3_core(const float* __restrict__ pts) {
    __shared__ u64    JX2_s[64], JY2_s[64], JZ2_s[64];  // dup'd (x,x) pairs, 1.5KB
    __shared__ u64    T2_s[4 * 4 * 64];  // [(w*4+t4)*64+j] = (Tjk[ka][j], Tjk[kb][j])  8KB
    __shared__ u64    P2_s[64 * 32];     // [j][lane] = {P(l,j), P(l+32,j)}  16KB
    __shared__ float4 D4_s[64];          // raw disp  1KB
    __shared__ float  red_s[4];

    int bx = blockIdx.x;
    int h  = bx & 1;
    int i  = (bx >> 1) & 63;
    int b  = bx >> 7;
    int k0 = h * 32;
    int tid = threadIdx.x, warp = tid >> 5, lane = tid & 31;

    const float* attq1 = g_att + (0 * BSZ + b) * NN;
    const float* attq2 = g_att + (1 * BSZ + b) * NN;
    const float* attq3 = g_att + (2 * BSZ + b) * NN;
    const float* Tjk   = g_att + (3 * BSZ + b) * NN;
    const float* Tjl   = g_att + (4 * BSZ + b) * NN;
    const float* Akl   = g_att + (5 * BSZ + b) * NN;

    // ---- prep ----
    {
        const float* pi = pts + (b * NP + i) * 3;
        float pix = pi[0], piy = pi[1], piz = pi[2];
        if (tid < 64) {
            const float* pp = pts + (b * NP + tid) * 3;
            float dx = pp[0] - pix, dy = pp[1] - piy, dz = pp[2] - piz;
            D4_s[tid]  = make_float4(dx, dy, dz, 0.f);
            JX2_s[tid] = pk2(dx, dx);
            JY2_s[tid] = pk2(dy, dy);
            JZ2_s[tid] = pk2(dz, dz);
        }
    }
    for (int idx = tid; idx < 1024; idx += 128) {       // Tjk (ka,kb) pairs
        int w = idx >> 8, r = idx & 255;
        int t = r >> 6,   j = r & 63;
        int ka = k0 + 8 * w + t;
        T2_s[idx] = pk2(Tjk[ka * 64 + j], Tjk[(ka + 4) * 64 + j]);
    }
    for (int t = tid; t < 2048; t += 128) {             // fused P pairs
        int lp = t & 31, j = t >> 5;
        float a1j = attq1[i * 64 + j];
        float lo = Tjl[lp * 64 + j]        + a1j + attq3[i * 64 + lp];
        float hi = Tjl[(lp + 32) * 64 + j] + a1j + attq3[i * 64 + lp + 32];
        P2_s[j * 32 + lp] = pk2(lo, hi);
    }
    __syncthreads();

    // per-lane packed dl for (l=lane, l+32) — loop-invariant
    float4 da = D4_s[lane], db = D4_s[lane + 32];
    u64 dlx2 = pk2(da.x, db.x);
    u64 dly2 = pk2(da.y, db.y);
    u64 dlz2 = pk2(da.z, db.z);
    u64 half2c = dup2(0.5f);
    u64 acca = pk2(0.f, 0.f);
    u64 accb = pk2(0.f, 0.f);

    #pragma unroll 1
    for (int t4 = 0; t4 < 4; t4++) {
        int ka = k0 + 8 * warp + t4;             // uniform within warp
        int kb = ka + 4;
        float4 dka = D4_s[ka];
        float4 dkb = D4_s[kb];
        float aika = __ldg(attq2 + i * 64 + ka);
        float aikb = __ldg(attq2 + i * 64 + kb);
        u64 base2a = pk2(aika + __ldg(Akl + ka * 64 + lane),
                         aika + __ldg(Akl + ka * 64 + lane + 32));
        u64 base2b = pk2(aikb + __ldg(Akl + kb * 64 + lane),
                         aikb + __ldg(Akl + kb * 64 + lane + 32));
        u64 cxa2 = fma2(dup2(dka.y), dlz2, mul2(dup2(-dka.z), dly2));
        u64 cya2 = fma2(dup2(dka.z), dlx2, mul2(dup2(-dka.x), dlz2));
        u64 cza2 = fma2(dup2(dka.x), dly2, mul2(dup2(-dka.y), dlx2));
        u64 cxb2 = fma2(dup2(dkb.y), dlz2, mul2(dup2(-dkb.z), dly2));
        u64 cyb2 = fma2(dup2(dkb.z), dlx2, mul2(dup2(-dkb.x), dlz2));
        u64 czb2 = fma2(dup2(dkb.x), dly2, mul2(dup2(-dkb.y), dlx2));
        const u64* Trow = T2_s + (warp * 4 + t4) * 64;

        #pragma unroll 8
        for (int j = 0; j < 64; j++) {
            u64 jx2 = JX2_s[j];                    // LDS.64 bcast, pre-dup'd
            u64 jy2 = JY2_s[j];
            u64 jz2 = JZ2_s[j];
            u64 tt  = Trow[j];                     // LDS.64 bcast (tka,tkb)
            u64 p2  = P2_s[j * 32 + lane];         // LDS.64 per-lane
            float tka, tkb; upk2(tka, tkb, tt);    // free (pair regs)
            u64 ea2 = add2(p2, add2(dup2(tka), base2a));
            u64 eb2 = add2(p2, add2(dup2(tkb), base2b));
            float ealo, eahi; upk2(ealo, eahi, ea2);
            float eblo, ebhi; upk2(eblo, ebhi, eb2);
            float ta_lo = tanh_(ealo), ta_hi = tanh_(eahi);
            float tb_lo = tanh_(eblo), tb_hi = tanh_(ebhi);
            u64 deta = fma2(jx2, cxa2, fma2(jy2, cya2, mul2(jz2, cza2)));
            u64 detb = fma2(jx2, cxb2, fma2(jy2, cyb2, mul2(jz2, czb2)));
            u64 d2a = mul2(deta, deta);
            u64 d2b = mul2(detb, detb);
            u64 g2a = fma2(pk2(ta_lo, ta_hi), half2c, half2c);
            u64 g2b = fma2(pk2(tb_lo, tb_hi), half2c, half2c);
            acca = fma2(d2a, g2a, acca);           // independent chains
            accb = fma2(d2b, g2b, accb);
        }
    }

    // ---- reduction ----
    u64 acc2 = add2(acca, accb);
    float alo, ahi; upk2(alo, ahi, acc2);
    float acc = alo + ahi;
    #pragma unroll
    for (int o = 16; o; o >>= 1) acc += __shfl_down_sync(0xffffffffu, acc, o);
    if (lane == 0) red_s[warp] = acc;
    __syncthreads();
    if (tid == 0) {
        float s = red_s[0] + red_s[1] + red_s[2] + red_s[3];
        g_anchor2[h * BSZ * NP + b * NP + i] = s;
    }
}

// ---------------- k4: pooled -> gelu MLP head (warp per batch) ----------------
__global__ void k4_head(const float* __restrict__ W1, const float* __restrict__ b1,
                        const float* __restrict__ W2, const float* __restrict__ b2,
                        float* __restrict__ out) {
    int warp = threadIdx.x >> 5, lane = threadIdx.x & 31;
    int b = warp;
    float s = g_anchor2[b * 64 + lane] + g_anchor2[b * 64 + lane + 32]
            + g_anchor2[BSZ * NP + b * 64 + lane] + g_anchor2[BSZ * NP + b * 64 + lane + 32];
    #pragma unroll
    for (int o = 16; o; o >>= 1) s += __shfl_xor_sync(0xffffffffu, s, o);
    float pooled = s * (1.f / 16777216.f);         // / (N^3 * N)
    float x  = fmaf(pooled, W1[lane], b1[lane]);   // lane = hidden unit
    float x3 = x * x * x;
    float t  = tanhf(0.7978845608028654f * fmaf(0.044715f, x3, x));
    float hc = 0.5f * x * (1.f + t);               // tanh-approx gelu
    float y  = hc * W2[lane];
    #pragma unroll
    for (int o = 16; o; o >>= 1) y += __shfl_xor_sync(0xffffffffu, y, o);
    if (lane == 0) out[b] = y + b2[0];
}

// ---------------- launch ----------------
extern "C" void kernel_launch(void* const* d_in, const int* in_sizes, int n_in,
                              void* d_out, int out_size) {
    const float* pts = (const float*)d_in[0];
    const float* Wq  = (const float*)d_in[1];
    const float* bq  = (const float*)d_in[2];
    const float* Wk1 = (const float*)d_in[3];
    const float* bk1 = (const float*)d_in[4];
    const float* Wk2 = (const float*)d_in[5];
    const float* bk2 = (const float*)d_in[6];
    const float* Wk3 = (const float*)d_in[7];
    const float* bk3 = (const float*)d_in[8];
    const float* W1  = (const float*)d_in[9];
    const float* b1  = (const float*)d_in[10];
    const float* W2  = (const float*)d_in[11];
    const float* b2  = (const float*)d_in[12];
    float* out = (float*)d_out;

    k12_att<<<BSZ * 6, 256>>>(pts, Wq, bq, Wk1, bk1, Wk2, bk2, Wk3, bk3);
    k_pad<<<1, 32>>>();                       // keeps ncu capture slot on k3
    k3_core<<<BSZ * NP * 2, 128>>>(pts);
    k4_head<<<1, BSZ * 32>>>(W1, b1, W2, b2, out);
}